// round 15
// baseline (speedup 1.0000x reference)
#include <cuda_runtime.h>
#include <math.h>

// ---------------- problem constants ----------------
#define N_ROWS   32768      // B*S = 8*4096
#define DIM      256
#define NCODES   8192
#define BETA_F   0.25f
#define ND       (N_ROWS * DIM)   // 8388608

// ---------------- device scratch (no allocs allowed) ----------------
__device__ float g_ee[NCODES];         // ||e_k||^2
__device__ int   g_idx[N_ROWS];        // argmin index per row
__device__ int   g_counts[NCODES];     // usage histogram
__device__ float g_partial[N_ROWS / 8];// per-block loss partial sums (4096)

// ---------------- packed f32x2 helpers ----------------
#define FMA_F32X2(d, a, b, c) \
    asm("fma.rn.f32x2 %0, %1, %2, %3;" : "=l"(d) : "l"(a), "l"(b), "l"(c))

#define UNPACK_F32X2(lo, hi, v) \
    asm("mov.b64 {%0, %1}, %2;" : "=r"(lo), "=r"(hi) : "l"(v))

// ---------------- kernel 0: zero the histogram ----------------
__global__ void zero_counts_kernel() {
    int i = blockIdx.x * blockDim.x + threadIdx.x;
    if (i < NCODES) g_counts[i] = 0;
}

// ---------------- tiny pad kernel: shifts argmin into ncu's capture slot ----
__global__ void pad_kernel() {}

// ---------------- kernel 1: ||e_k||^2, one warp per code ----------------
__global__ __launch_bounds__(256) void ee_kernel(const float* __restrict__ embed) {
    int warp = (blockIdx.x * blockDim.x + threadIdx.x) >> 5;
    int lane = threadIdx.x & 31;
    if (warp >= NCODES) return;
    const float4* p = reinterpret_cast<const float4*>(embed + (size_t)warp * DIM);
    float s = 0.f;
    #pragma unroll
    for (int k = 0; k < 2; ++k) {
        float4 v = p[k * 32 + lane];
        s += v.x * v.x + v.y * v.y + v.z * v.z + v.w * v.w;
    }
    #pragma unroll
    for (int off = 16; off > 0; off >>= 1)
        s += __shfl_xor_sync(0xffffffffu, s, off);
    if (lane == 0) g_ee[warp] = s;
}

// ---------------- kernel 2: fused GEMM + argmin (v4b: row-paired acc) -------
// 128 rows x 128 codes per tile, 256 threads (16x16), 8x8 per-thread tile.
// Accumulators pair ADJACENT ROWS in one f32x2 register:
//   acc2[p][j] = (dot(row 2p), dot(row 2p+1)) for column j.
// A pairs come straight from As (contiguous rows, 2 LDS.128 per bd, NO movs,
// NO duplication). B is stored duplicated in shared (Bs2[d][2*col]) so (b,b)
// pairs come from LDS.128. Inner loop per bd: 6 LDS.128 + 32 FFMA2, pure.
// Flattened (codeTile, dChunk) loop, register prefetch + double-buffered
// shared, one barrier per chunk.
#define BM 128
#define BN 128
#define BD 16
#define ASTR 132                 // A row stride (floats): 128 + pad4
#define BSTR 264                 // dup'd B row stride (floats): 256 + pad8
#define NUM_CB  (NCODES / BN)            // 64
#define CHUNKS  (NUM_CB * (DIM / BD))    // 1024

__global__ __launch_bounds__(256, 2)
void argmin_kernel(const float* __restrict__ z, const float* __restrict__ embed) {
    __shared__ __align__(16) float As[2][BD][ASTR];   // [d][row]
    __shared__ __align__(16) float Bs2[2][BD][BSTR];  // [d][2*code] duplicated
    __shared__ float ee_s[2][BN];
    __shared__ float red_d[BM][17];
    __shared__ int   red_i[BM][17];

    const int tid = threadIdx.x;
    const int tx  = tid & 15;          // column group 0..15
    const int ty  = tid >> 4;          // row group 0..15
    const int rowBase = blockIdx.x * BM;

    // global->shared mapping: thread loads 2 float4 per matrix per chunk,
    // row rA, d-offsets q0..q0+3 and q1..q1+3 within the 16-wide chunk.
    const int rA = tid >> 1;
    const int q0 = (tid & 1) * 8;
    const int q1 = q0 + 4;

    // running argmin state lives in shared (epilogue-only access)
    #pragma unroll
    for (int i = 0; i < 8; ++i) {
        red_d[ty * 8 + i][tx] = 3.4e38f;
        red_i[ty * 8 + i][tx] = 0;
    }

    const float* zrow = z + (size_t)(rowBase + rA) * DIM;

    float4 a_r0, a_r1, b_r0, b_r1;
    float  ee_r = 0.f;

    // ---- prologue: load + store chunk 0 (cb=0, db=0) ----
    a_r0 = *reinterpret_cast<const float4*>(zrow + q0);
    a_r1 = *reinterpret_cast<const float4*>(zrow + q1);
    {
        const float* brow = embed + (size_t)rA * DIM;
        b_r0 = *reinterpret_cast<const float4*>(brow + q0);
        b_r1 = *reinterpret_cast<const float4*>(brow + q1);
    }
    if (tid < BN) ee_r = g_ee[tid];

    {
        As[0][q0 + 0][rA] = a_r0.x; As[0][q0 + 1][rA] = a_r0.y;
        As[0][q0 + 2][rA] = a_r0.z; As[0][q0 + 3][rA] = a_r0.w;
        As[0][q1 + 0][rA] = a_r1.x; As[0][q1 + 1][rA] = a_r1.y;
        As[0][q1 + 2][rA] = a_r1.z; As[0][q1 + 3][rA] = a_r1.w;
        const int cb2 = 2 * rA;
        *reinterpret_cast<float2*>(&Bs2[0][q0 + 0][cb2]) = make_float2(b_r0.x, b_r0.x);
        *reinterpret_cast<float2*>(&Bs2[0][q0 + 1][cb2]) = make_float2(b_r0.y, b_r0.y);
        *reinterpret_cast<float2*>(&Bs2[0][q0 + 2][cb2]) = make_float2(b_r0.z, b_r0.z);
        *reinterpret_cast<float2*>(&Bs2[0][q0 + 3][cb2]) = make_float2(b_r0.w, b_r0.w);
        *reinterpret_cast<float2*>(&Bs2[0][q1 + 0][cb2]) = make_float2(b_r1.x, b_r1.x);
        *reinterpret_cast<float2*>(&Bs2[0][q1 + 1][cb2]) = make_float2(b_r1.y, b_r1.y);
        *reinterpret_cast<float2*>(&Bs2[0][q1 + 2][cb2]) = make_float2(b_r1.z, b_r1.z);
        *reinterpret_cast<float2*>(&Bs2[0][q1 + 3][cb2]) = make_float2(b_r1.w, b_r1.w);
        if (tid < BN) ee_s[0][tid] = ee_r;
    }
    __syncthreads();

    // acc2[p][j]: row-pair p (rows ty*8+2p, ty*8+2p+1), thread-col j
    unsigned long long acc2[4][8];

    #pragma unroll 1
    for (int c = 0; c < CHUNKS; ++c) {
        const int buf = c & 1;
        const int cb  = c >> 4;

        // ---- prefetch chunk c+1 into registers ----
        const int c1 = c + 1;
        const bool have_next = (c1 < CHUNKS);
        if (have_next) {
            const int cb1 = c1 >> 4;
            const int db1 = (c1 & 15) * BD;
            a_r0 = *reinterpret_cast<const float4*>(zrow + db1 + q0);
            a_r1 = *reinterpret_cast<const float4*>(zrow + db1 + q1);
            const float* brow = embed + (size_t)(cb1 * BN + rA) * DIM + db1;
            b_r0 = *reinterpret_cast<const float4*>(brow + q0);
            b_r1 = *reinterpret_cast<const float4*>(brow + q1);
            if (((c1 & 15) == 0) && tid < BN) ee_r = g_ee[cb1 * BN + tid];
        }

        // ---- zero accumulators at the start of each code tile ----
        if ((c & 15) == 0) {
            #pragma unroll
            for (int p = 0; p < 4; ++p)
                #pragma unroll
                for (int j = 0; j < 8; ++j) acc2[p][j] = 0ull;
        }

        // ---- compute: 16 d-steps, 8x8 outer product, pure FFMA2 ----
        #pragma unroll
        for (int bd = 0; bd < BD; ++bd) {
            // A row pairs: rows ty*8 .. ty*8+7 -> 4 packed (r,r+1) pairs
            ulonglong2 ap01 = *reinterpret_cast<const ulonglong2*>(&As[buf][bd][ty * 8]);
            ulonglong2 ap23 = *reinterpret_cast<const ulonglong2*>(&As[buf][bd][ty * 8 + 4]);
            // B dup pairs: cols tx*4..+3 (dup idx 8*tx) and 64+tx*4..+3
            // (dup idx 128+8*tx), each element stored as (b,b)
            ulonglong2 bq0 = *reinterpret_cast<const ulonglong2*>(&Bs2[buf][bd][8 * tx]);
            ulonglong2 bq1 = *reinterpret_cast<const ulonglong2*>(&Bs2[buf][bd][8 * tx + 4]);
            ulonglong2 bq2 = *reinterpret_cast<const ulonglong2*>(&Bs2[buf][bd][128 + 8 * tx]);
            ulonglong2 bq3 = *reinterpret_cast<const ulonglong2*>(&Bs2[buf][bd][128 + 8 * tx + 4]);
            #define COLFMA(j, bp)                                     \
                FMA_F32X2(acc2[0][j], ap01.x, bp, acc2[0][j]);        \
                FMA_F32X2(acc2[1][j], ap01.y, bp, acc2[1][j]);        \
                FMA_F32X2(acc2[2][j], ap23.x, bp, acc2[2][j]);        \
                FMA_F32X2(acc2[3][j], ap23.y, bp, acc2[3][j]);
            COLFMA(0, bq0.x) COLFMA(1, bq0.y)
            COLFMA(2, bq1.x) COLFMA(3, bq1.y)
            COLFMA(4, bq2.x) COLFMA(5, bq2.y)
            COLFMA(6, bq3.x) COLFMA(7, bq3.y)
            #undef COLFMA
        }

        // ---- epilogue at end of each code tile: fold into running argmin ----
        // Columns visited in ascending order; strict < keeps the lowest
        // index, matching jnp.argmin tie-breaking.
        if ((c & 15) == 15) {
            const int eb = cb & 1;
            #pragma unroll
            for (int p = 0; p < 4; ++p) {
                const int r0 = ty * 8 + 2 * p;
                float bd0 = red_d[r0][tx],     bd1 = red_d[r0 + 1][tx];
                int   bi0 = red_i[r0][tx],     bi1 = red_i[r0 + 1][tx];
                #pragma unroll
                for (int j = 0; j < 8; ++j) {
                    unsigned int u0, u1;
                    UNPACK_F32X2(u0, u1, acc2[p][j]);   // u0=row r0, u1=row r0+1
                    const int eidx = (j < 4) ? (tx * 4 + j) : (64 + tx * 4 + (j - 4));
                    const int col  = cb * BN + eidx;
                    const float ee = ee_s[eb][eidx];
                    float d0 = fmaf(-2.f, __uint_as_float(u0), ee);
                    float d1 = fmaf(-2.f, __uint_as_float(u1), ee);
                    if (d0 < bd0) { bd0 = d0; bi0 = col; }
                    if (d1 < bd1) { bd1 = d1; bi1 = col; }
                }
                red_d[r0][tx] = bd0;     red_i[r0][tx] = bi0;
                red_d[r0 + 1][tx] = bd1; red_i[r0 + 1][tx] = bi1;
            }
        }

        // ---- store prefetched chunk into the other buffer ----
        if (have_next) {
            const int nb = buf ^ 1;
            As[nb][q0 + 0][rA] = a_r0.x; As[nb][q0 + 1][rA] = a_r0.y;
            As[nb][q0 + 2][rA] = a_r0.z; As[nb][q0 + 3][rA] = a_r0.w;
            As[nb][q1 + 0][rA] = a_r1.x; As[nb][q1 + 1][rA] = a_r1.y;
            As[nb][q1 + 2][rA] = a_r1.z; As[nb][q1 + 3][rA] = a_r1.w;
            const int cb2 = 2 * rA;
            *reinterpret_cast<float2*>(&Bs2[nb][q0 + 0][cb2]) = make_float2(b_r0.x, b_r0.x);
            *reinterpret_cast<float2*>(&Bs2[nb][q0 + 1][cb2]) = make_float2(b_r0.y, b_r0.y);
            *reinterpret_cast<float2*>(&Bs2[nb][q0 + 2][cb2]) = make_float2(b_r0.z, b_r0.z);
            *reinterpret_cast<float2*>(&Bs2[nb][q0 + 3][cb2]) = make_float2(b_r0.w, b_r0.w);
            *reinterpret_cast<float2*>(&Bs2[nb][q1 + 0][cb2]) = make_float2(b_r1.x, b_r1.x);
            *reinterpret_cast<float2*>(&Bs2[nb][q1 + 1][cb2]) = make_float2(b_r1.y, b_r1.y);
            *reinterpret_cast<float2*>(&Bs2[nb][q1 + 2][cb2]) = make_float2(b_r1.z, b_r1.z);
            *reinterpret_cast<float2*>(&Bs2[nb][q1 + 3][cb2]) = make_float2(b_r1.w, b_r1.w);
            if (((c1 & 15) == 0) && tid < BN)
                ee_s[(c1 >> 4) & 1][tid] = ee_r;
        }
        __syncthreads();
    }

    // ---- final cross-thread reduction over the 16 column groups per row ----
    if (tid < BM) {
        float bd = red_d[tid][0];
        int   bi = red_i[tid][0];
        #pragma unroll
        for (int t = 1; t < 16; ++t) {
            float dd = red_d[tid][t];
            int   ii = red_i[tid][t];
            if (dd < bd || (dd == bd && ii < bi)) { bd = dd; bi = ii; }
        }
        g_idx[rowBase + tid] = bi;
    }
}

// ---------------- kernel 3: gather z_q, loss partials, histogram, idx ----
__global__ __launch_bounds__(256)
void gather_kernel(const float* __restrict__ z, const float* __restrict__ embed,
                   float* __restrict__ out, int write_idx) {
    __shared__ float sh[8];
    int w = threadIdx.x >> 5, lane = threadIdx.x & 31;
    int row = blockIdx.x * 8 + w;
    int idx = g_idx[row];
    const float4* pe = reinterpret_cast<const float4*>(embed + (size_t)idx * DIM);
    const float4* pz = reinterpret_cast<const float4*>(z + (size_t)row * DIM);
    float4*       po = reinterpret_cast<float4*>(out + (size_t)row * DIM);
    float s = 0.f;
    #pragma unroll
    for (int k = 0; k < 2; ++k) {
        float4 e  = pe[k * 32 + lane];
        float4 zz = pz[k * 32 + lane];
        po[k * 32 + lane] = e;   // z_q_st value == z_q
        float dx = e.x - zz.x, dy = e.y - zz.y, dz2 = e.z - zz.z, dw = e.w - zz.w;
        s += dx * dx + dy * dy + dz2 * dz2 + dw * dw;
    }
    #pragma unroll
    for (int off = 16; off > 0; off >>= 1)
        s += __shfl_xor_sync(0xffffffffu, s, off);
    if (lane == 0) {
        sh[w] = s;
        atomicAdd(&g_counts[idx], 1);          // int atomics: deterministic
        if (write_idx) out[ND + 2 + row] = (float)idx;
    }
    __syncthreads();
    if (threadIdx.x == 0) {
        float t = 0.f;
        #pragma unroll
        for (int i = 0; i < 8; ++i) t += sh[i];   // fixed order: deterministic
        g_partial[blockIdx.x] = t;
    }
}

// ---------------- kernel 4: loss + perplexity (single block) ----------------
__global__ __launch_bounds__(256)
void finalize_kernel(float* __restrict__ out, int write_scalars) {
    __shared__ float sh[256];
    int tid = threadIdx.x;

    float s = 0.f;
    for (int i = tid; i < N_ROWS / 8; i += 256) s += g_partial[i];
    sh[tid] = s; __syncthreads();
    for (int off = 128; off > 0; off >>= 1) {
        if (tid < off) sh[tid] += sh[tid + off];
        __syncthreads();
    }
    float loss = sh[0] * (BETA_F / (float)ND);
    __syncthreads();

    float ps = 0.f;
    const float invN = 1.f / (float)N_ROWS;
    for (int i = tid; i < NCODES; i += 256) {
        float p = (float)g_counts[i] * invN;
        ps += p * logf(p + 1e-12f);
    }
    sh[tid] = ps; __syncthreads();
    for (int off = 128; off > 0; off >>= 1) {
        if (tid < off) sh[tid] += sh[tid + off];
        __syncthreads();
    }
    if (tid == 0 && write_scalars) {
        out[ND]     = loss;
        out[ND + 1] = expf(-sh[0]);
    }
}

// ---------------- launch ----------------
extern "C" void kernel_launch(void* const* d_in, const int* in_sizes, int n_in,
                              void* d_out, int out_size) {
    const float* z     = (const float*)d_in[0];   // [B,S,D] fp32
    const float* embed = (const float*)d_in[1];   // [K,D]  fp32
    float* out = (float*)d_out;
    (void)in_sizes; (void)n_in;

    int write_scalars = (out_size >= ND + 2) ? 1 : 0;
    int write_idx     = (out_size >= ND + 2 + N_ROWS) ? 1 : 0;

    zero_counts_kernel<<<(NCODES + 255) / 256, 256>>>();
    ee_kernel<<<NCODES / 8, 256>>>(embed);
    pad_kernel<<<1, 32>>>();   // shifts argmin into ncu's fixed capture slot
    argmin_kernel<<<N_ROWS / BM, 256>>>(z, embed);
    gather_kernel<<<N_ROWS / 8, 256>>>(z, embed, out, write_idx);
    finalize_kernel<<<1, 256>>>(out, write_scalars);
}